// round 8
// baseline (speedup 1.0000x reference)
#include <cuda_runtime.h>
#include <cstdint>

// out[i] = W[inputs[i] - 1];  N = 16384*200 = 3,276,800;  W: 200 floats.
// Index dtype probe: idx_raw[1]==0 -> int64 (high word of elem 0), else int32.
//
// One-wave launch: 800 CTAs x 256 thr, 2 units/thread (unit = 8 out elems).
// 800*256*2*8 = N exactly; 800 <= 148*8 concurrent -> single wave, no tail.
// 256-bit global ops with L2 policies (evict_last idx / evict_first out).
// All index loads front-batched before the smem W fill (latency overlap).

#define N_TOTAL   (16384 * 200)
#define MAX_RANKS 200
#define TPB       256
#define NBLK      800
#define NTHREADS  ((long long)NBLK * TPB)   // 204,800; 2 units each

struct V8 { uint32_t r0,r1,r2,r3,r4,r5,r6,r7; };

__device__ __forceinline__ V8 ldg_pin8(const void* p) {
    V8 v;
    asm volatile("ld.global.nc.L2::evict_last.v8.b32 "
                 "{%0,%1,%2,%3,%4,%5,%6,%7}, [%8];"
                 : "=r"(v.r0), "=r"(v.r1), "=r"(v.r2), "=r"(v.r3),
                   "=r"(v.r4), "=r"(v.r5), "=r"(v.r6), "=r"(v.r7)
                 : "l"(p));
    return v;
}

__device__ __forceinline__ void stg_stream8(void* p, const float* f) {
    asm volatile("st.global.L2::evict_first.v8.b32 "
                 "[%0], {%1,%2,%3,%4,%5,%6,%7,%8};"
                 :: "l"(p),
                    "f"(f[0]), "f"(f[1]), "f"(f[2]), "f"(f[3]),
                    "f"(f[4]), "f"(f[5]), "f"(f[6]), "f"(f[7])
                 : "memory");
}

__global__ __launch_bounds__(TPB)
void bias_gather_kernel(const uint32_t* __restrict__ idx_raw,
                        const float* __restrict__ W,
                        float* __restrict__ out)
{
    // 32-way replicated W: sW[rank*32 + lane] -> bank == lane, conflict-free.
    __shared__ float sW[MAX_RANKS * 32];

    const int tid  = threadIdx.x;
    const int lane = tid & 31;
    const int wid  = tid >> 5;

    const long long u0 = (long long)blockIdx.x * TPB + tid;  // unit 0
    const long long u1 = u0 + NTHREADS;                      // unit 1

    // ---- Front-batch ALL global index loads (max MLP, overlap W fill) ----
    const uint32_t probe = idx_raw[1];          // 0 => int64 indices
    const bool is64 = (probe == 0u);

    const char* ib = reinterpret_cast<const char*>(idx_raw);
    V8 a0, a1, b0, b1;
    if (is64) {
        a0 = ldg_pin8(ib + u0 * 64);
        a1 = ldg_pin8(ib + u0 * 64 + 32);
        b0 = ldg_pin8(ib + u1 * 64);
        b1 = ldg_pin8(ib + u1 * 64 + 32);
    } else {
        a0 = ldg_pin8(ib + u0 * 32);
        b0 = ldg_pin8(ib + u1 * 32);
    }

    // ---- Fill replicated W while index loads are in flight ----
    #pragma unroll
    for (int k = wid; k < MAX_RANKS; k += TPB / 32) {
        float v = W[k];                 // warp-uniform addr: 1 sector
        sW[k * 32 + lane] = v;          // conflict-free STS
    }
    __syncthreads();

    // ---- Conflict-free gathers + two streaming 256-bit stores ----
    float r0[8], r1[8];
    if (is64) {
        r0[0] = sW[((int)a0.r0 - 1) * 32 + lane];
        r0[1] = sW[((int)a0.r2 - 1) * 32 + lane];
        r0[2] = sW[((int)a0.r4 - 1) * 32 + lane];
        r0[3] = sW[((int)a0.r6 - 1) * 32 + lane];
        r0[4] = sW[((int)a1.r0 - 1) * 32 + lane];
        r0[5] = sW[((int)a1.r2 - 1) * 32 + lane];
        r0[6] = sW[((int)a1.r4 - 1) * 32 + lane];
        r0[7] = sW[((int)a1.r6 - 1) * 32 + lane];

        r1[0] = sW[((int)b0.r0 - 1) * 32 + lane];
        r1[1] = sW[((int)b0.r2 - 1) * 32 + lane];
        r1[2] = sW[((int)b0.r4 - 1) * 32 + lane];
        r1[3] = sW[((int)b0.r6 - 1) * 32 + lane];
        r1[4] = sW[((int)b1.r0 - 1) * 32 + lane];
        r1[5] = sW[((int)b1.r2 - 1) * 32 + lane];
        r1[6] = sW[((int)b1.r4 - 1) * 32 + lane];
        r1[7] = sW[((int)b1.r6 - 1) * 32 + lane];
    } else {
        r0[0] = sW[((int)a0.r0 - 1) * 32 + lane];
        r0[1] = sW[((int)a0.r1 - 1) * 32 + lane];
        r0[2] = sW[((int)a0.r2 - 1) * 32 + lane];
        r0[3] = sW[((int)a0.r3 - 1) * 32 + lane];
        r0[4] = sW[((int)a0.r4 - 1) * 32 + lane];
        r0[5] = sW[((int)a0.r5 - 1) * 32 + lane];
        r0[6] = sW[((int)a0.r6 - 1) * 32 + lane];
        r0[7] = sW[((int)a0.r7 - 1) * 32 + lane];

        r1[0] = sW[((int)b0.r0 - 1) * 32 + lane];
        r1[1] = sW[((int)b0.r1 - 1) * 32 + lane];
        r1[2] = sW[((int)b0.r2 - 1) * 32 + lane];
        r1[3] = sW[((int)b0.r3 - 1) * 32 + lane];
        r1[4] = sW[((int)b0.r4 - 1) * 32 + lane];
        r1[5] = sW[((int)b0.r5 - 1) * 32 + lane];
        r1[6] = sW[((int)b0.r6 - 1) * 32 + lane];
        r1[7] = sW[((int)b0.r7 - 1) * 32 + lane];
    }

    char* ob = reinterpret_cast<char*>(out);
    stg_stream8(ob + u0 * 32, r0);
    stg_stream8(ob + u1 * 32, r1);
}

extern "C" void kernel_launch(void* const* d_in, const int* in_sizes, int n_in,
                              void* d_out, int out_size)
{
    const uint32_t* idx = (const uint32_t*)d_in[0];  // inputs [16384, 200]
    const float*    W   = (const float*)d_in[1];     // [200, 1]
    float*          out = (float*)d_out;

    bias_gather_kernel<<<NBLK, TPB>>>(idx, W, out);
}

// round 9
// speedup vs baseline: 1.1074x; 1.1074x over previous
#include <cuda_runtime.h>
#include <cstdint>

// out[i] = W[inputs[i] - 1];  N = 16384*200 = 3,276,800;  W: 200 floats.
// Index dtype probe: idx_raw[1]==0 -> int64 (high word of elem 0), else int32.
//
// No-smem variant of the best (R7) kernel: 800 CTAs x 512 thr, 1 unit/thread
// (unit = 8 out elems, exact cover). 256-bit loads/stores with L2 policies.
// W gathered directly via __ldg: 800B = 7 lines, L1-resident after warmup,
// so each CTA skips the smem fill + __syncthreads prologue entirely.

#define N_TOTAL   (16384 * 200)
#define MAX_RANKS 200
#define TPB       512
#define NBLK      (N_TOTAL / (TPB * 8))   // 800

struct V8 { uint32_t r0,r1,r2,r3,r4,r5,r6,r7; };

__device__ __forceinline__ V8 ldg_pin8(const void* p) {
    V8 v;
    asm volatile("ld.global.nc.L2::evict_last.v8.b32 "
                 "{%0,%1,%2,%3,%4,%5,%6,%7}, [%8];"
                 : "=r"(v.r0), "=r"(v.r1), "=r"(v.r2), "=r"(v.r3),
                   "=r"(v.r4), "=r"(v.r5), "=r"(v.r6), "=r"(v.r7)
                 : "l"(p));
    return v;
}

__device__ __forceinline__ void stg_stream8(void* p, const float* f) {
    asm volatile("st.global.L2::evict_first.v8.b32 "
                 "[%0], {%1,%2,%3,%4,%5,%6,%7,%8};"
                 :: "l"(p),
                    "f"(f[0]), "f"(f[1]), "f"(f[2]), "f"(f[3]),
                    "f"(f[4]), "f"(f[5]), "f"(f[6]), "f"(f[7])
                 : "memory");
}

__global__ __launch_bounds__(TPB)
void bias_gather_kernel(const uint32_t* __restrict__ idx_raw,
                        const float* __restrict__ W,
                        float* __restrict__ out)
{
    const long long u = (long long)blockIdx.x * TPB + threadIdx.x; // 409,600

    const uint32_t probe = idx_raw[1];      // 0 => int64 indices
    const char* ib = reinterpret_cast<const char*>(idx_raw);

    float r[8];
    if (probe == 0u) {
        // int64: 8 indices = 64B = two v8.b32 loads; low words at even regs.
        V8 a = ldg_pin8(ib + u * 64);
        V8 b = ldg_pin8(ib + u * 64 + 32);
        r[0] = __ldg(W + (int)a.r0 - 1);
        r[1] = __ldg(W + (int)a.r2 - 1);
        r[2] = __ldg(W + (int)a.r4 - 1);
        r[3] = __ldg(W + (int)a.r6 - 1);
        r[4] = __ldg(W + (int)b.r0 - 1);
        r[5] = __ldg(W + (int)b.r2 - 1);
        r[6] = __ldg(W + (int)b.r4 - 1);
        r[7] = __ldg(W + (int)b.r6 - 1);
    } else {
        // int32: 8 indices = 32B = one v8.b32 load.
        V8 a = ldg_pin8(ib + u * 32);
        r[0] = __ldg(W + (int)a.r0 - 1);
        r[1] = __ldg(W + (int)a.r1 - 1);
        r[2] = __ldg(W + (int)a.r2 - 1);
        r[3] = __ldg(W + (int)a.r3 - 1);
        r[4] = __ldg(W + (int)a.r4 - 1);
        r[5] = __ldg(W + (int)a.r5 - 1);
        r[6] = __ldg(W + (int)a.r6 - 1);
        r[7] = __ldg(W + (int)a.r7 - 1);
    }

    stg_stream8(reinterpret_cast<char*>(out) + u * 32, r);
}

extern "C" void kernel_launch(void* const* d_in, const int* in_sizes, int n_in,
                              void* d_out, int out_size)
{
    const uint32_t* idx = (const uint32_t*)d_in[0];  // inputs [16384, 200]
    const float*    W   = (const float*)d_in[1];     // [200, 1]
    float*          out = (float*)d_out;

    bias_gather_kernel<<<NBLK, TPB>>>(idx, W, out);
}